// round 6
// baseline (speedup 1.0000x reference)
#include <cuda_runtime.h>
#include <math.h>
#include <stdint.h>

// Problem constants (fixed by the dataset)
#define NN 16384      // nodes per set
#define DD 256        // model dim
#define EE 131072     // edges per relation
#define HH 8          // heads
#define HDIM 32       // head dim
#define IM 682        // SwiGLU intermediate

// ---------------- scratch (static device globals; no allocations) ----------
__device__ float g_q[NN * DD];          // q (contiguous [n][h*32+d])
__device__ float g_k[NN * DD];          // k
__device__ float g_v[NN * DD];          // v
__device__ float g_kvtmp[NN * 3 * DD];  // raw interleaved kv / qkv GEMM output
__device__ float g_scores[EE * HH];
__device__ float g_s[NN * HH];
__device__ float g_agg[NN * DD];
__device__ float g_x1[NN * DD];
__device__ float g_x2[NN * DD];
__device__ float g_tmp[NN * DD];
__device__ float g_h1[NN * IM];
__device__ float g_h2[NN * IM];

__device__ __forceinline__ uint32_t f2tf32(float f) {
    uint32_t r;
    asm("cvt.rna.tf32.f32 %0, %1;" : "=r"(r) : "f"(f));
    return r;
}

// ---------------- TF32 tensor-core GEMM (R4 version — proven) ----------------
// C[M,N] = A[M,K] @ B[K,N], row-major fp32 in/out, tf32 mma.sync compute.
// 128x128 block tile, BK=32, 256 threads (8 warps), warp tile 64x32.
#define BM 128
#define BN 128
#define BK 32
#define PAD 132   // padded row length (floats) for conflict-free frag loads

__global__ __launch_bounds__(256)
void tgemm_kernel(const float* __restrict__ A, const float* __restrict__ B,
                  float* __restrict__ C, int M, int N, int K) {
    __shared__ uint32_t As[BK][PAD];   // As[k][m], tf32 bits
    __shared__ uint32_t Bs[BK][PAD];   // Bs[k][n], tf32 bits

    const int tid  = threadIdx.x;
    const int lane = tid & 31;
    const int wid  = tid >> 5;            // 0..7
    const int warpM = wid & 1;            // 2 warps along M
    const int warpN = wid >> 1;           // 4 warps along N
    const int g   = lane >> 2;            // groupID 0..7
    const int tig = lane & 3;             // thread-in-group 0..3

    const int rowBase = blockIdx.y * BM;
    const int colBase = blockIdx.x * BN;

    float acc[4][4][4];
    #pragma unroll
    for (int i = 0; i < 4; i++)
        #pragma unroll
        for (int j = 0; j < 4; j++)
            #pragma unroll
            for (int r = 0; r < 4; r++) acc[i][j][r] = 0.0f;

    for (int k0 = 0; k0 < K; k0 += BK) {
        __syncthreads();
        // ---- load A tile: BM x BK, transposed into As[k][m], float2 global loads
        #pragma unroll
        for (int i = 0; i < 8; i++) {
            int l  = tid + i * 256;       // 0..2047 float2 slots
            int r  = l >> 4;              // 0..127
            int c2 = l & 15;              // 0..15 -> k pair
            int gr = rowBase + r;
            int gk = k0 + 2 * c2;
            float2 v = make_float2(0.0f, 0.0f);
            if (gr < M && gk < K) v = *(const float2*)(A + (size_t)gr * K + gk);
            As[2 * c2][r]     = f2tf32(v.x);
            As[2 * c2 + 1][r] = f2tf32(v.y);
        }
        // ---- load B tile: BK x BN into Bs[k][n], float2 global loads
        #pragma unroll
        for (int i = 0; i < 8; i++) {
            int l  = tid + i * 256;
            int kk = l >> 6;              // 0..31
            int c2 = l & 63;              // 0..63 -> n pair
            int gk = k0 + kk;
            int gc = colBase + 2 * c2;
            float2 v = make_float2(0.0f, 0.0f);
            if (gk < K && gc < N) v = *(const float2*)(B + (size_t)gk * N + gc);
            Bs[kk][2 * c2]     = f2tf32(v.x);
            Bs[kk][2 * c2 + 1] = f2tf32(v.y);
        }
        __syncthreads();

        // ---- compute: 4 k-atoms of 8
        #pragma unroll
        for (int ka = 0; ka < 4; ka++) {
            const int kb = ka * 8;
            uint32_t a[4][4], b[4][2];
            #pragma unroll
            for (int ma = 0; ma < 4; ma++) {
                int m0 = warpM * 64 + ma * 16;
                a[ma][0] = As[kb + tig][m0 + g];
                a[ma][1] = As[kb + tig][m0 + g + 8];
                a[ma][2] = As[kb + tig + 4][m0 + g];
                a[ma][3] = As[kb + tig + 4][m0 + g + 8];
            }
            #pragma unroll
            for (int na = 0; na < 4; na++) {
                int n0 = warpN * 32 + na * 8;
                b[na][0] = Bs[kb + tig][n0 + g];
                b[na][1] = Bs[kb + tig + 4][n0 + g];
            }
            #pragma unroll
            for (int ma = 0; ma < 4; ma++)
                #pragma unroll
                for (int na = 0; na < 4; na++) {
                    asm volatile(
                        "mma.sync.aligned.m16n8k8.row.col.f32.tf32.tf32.f32 "
                        "{%0,%1,%2,%3}, {%4,%5,%6,%7}, {%8,%9}, {%0,%1,%2,%3};\n"
                        : "+f"(acc[ma][na][0]), "+f"(acc[ma][na][1]),
                          "+f"(acc[ma][na][2]), "+f"(acc[ma][na][3])
                        : "r"(a[ma][0]), "r"(a[ma][1]), "r"(a[ma][2]), "r"(a[ma][3]),
                          "r"(b[na][0]), "r"(b[na][1]));
                }
        }
    }

    // ---- store C (float2 per row-half of each atom); N even -> alignment OK
    #pragma unroll
    for (int ma = 0; ma < 4; ma++) {
        int r0 = rowBase + warpM * 64 + ma * 16 + g;
        #pragma unroll
        for (int na = 0; na < 4; na++) {
            int c = colBase + warpN * 32 + na * 8 + tig * 2;
            if (c < N) {
                if (r0 < M)
                    *(float2*)(C + (size_t)r0 * N + c) = make_float2(acc[ma][na][0], acc[ma][na][1]);
                if (r0 + 8 < M)
                    *(float2*)(C + (size_t)(r0 + 8) * N + c) = make_float2(acc[ma][na][2], acc[ma][na][3]);
            }
        }
    }
}

// ---------------- de-interleave kernels -------------------------------------
// kv [n][h*64 + 2d + {0:k,1:v}] -> k[n][h*32+d], v[n][h*32+d]
__global__ void deint_kv_kernel(const float* __restrict__ kv,
                                float* __restrict__ k, float* __restrict__ v) {
    int i = blockIdx.x * blockDim.x + threadIdx.x;   // NN*DD threads
    int n = i >> 8, j = i & 255;
    int h = j >> 5, d = j & 31;
    float2 p = *(const float2*)(kv + (size_t)n * 512 + h * 64 + 2 * d);
    k[i] = p.x;
    v[i] = p.y;
}

// qkv [n][h*96 + 3d + {0:q,1:k,2:v}] -> q,k,v [n][h*32+d]
__global__ void deint_qkv_kernel(const float* __restrict__ qkv,
                                 float* __restrict__ q, float* __restrict__ k,
                                 float* __restrict__ v) {
    int i = blockIdx.x * blockDim.x + threadIdx.x;   // NN*DD threads
    int n = i >> 8, j = i & 255;
    int h = j >> 5, d = j & 31;
    const float* p = qkv + (size_t)n * 768 + h * 96 + 3 * d;
    q[i] = p[0];
    k[i] = p[1];
    v[i] = p[2];
}

// ---------------- reset: agg=0, s=0 -----------------------------------------
__global__ void reset_kernel(float* s, float* agg) {
    int i = blockIdx.x * blockDim.x + threadIdx.x;   // NN*DD threads
    agg[i] = 0.0f;
    if (i < NN * HH) s[i] = 0.0f;
}

// ---------------- reciprocal of softmax denominators ------------------------
__global__ void rcp_kernel(float* __restrict__ s) {
    int i = blockIdx.x * blockDim.x + threadIdx.x;
    if (i < NN * HH) s[i] = __frcp_rn(s[i]);
}

// ---------------- edge kernels (contiguous [n][h*32+d] layouts) -------------
// warp per edge; 4 lanes per head; lane handles 8 consecutive dims.
// No max-subtraction: scores are O(10), exp is safe in fp32; softmax is
// shift-invariant so the result matches the reference.
__global__ void cross_scores_kernel(const float* __restrict__ Q, const float* __restrict__ Kk,
                                    const int* __restrict__ src, const int* __restrict__ dst,
                                    float* __restrict__ scores, float* __restrict__ s,
                                    float scale) {
    int e = (blockIdx.x * blockDim.x + threadIdx.x) >> 5;
    int lane = threadIdx.x & 31;
    if (e >= EE) return;
    int sn = src[e], tn = dst[e];
    const float4* q4 = (const float4*)(Q  + (size_t)tn * DD);
    const float4* k4 = (const float4*)(Kk + (size_t)sn * DD);
    float4 qa = q4[2 * lane], qb = q4[2 * lane + 1];
    float4 ka = k4[2 * lane], kb = k4[2 * lane + 1];
    float p = qa.x * ka.x + qa.y * ka.y + qa.z * ka.z + qa.w * ka.w
            + qb.x * kb.x + qb.y * kb.y + qb.z * kb.z + qb.w * kb.w;
    p += __shfl_xor_sync(0xFFFFFFFFu, p, 1);
    p += __shfl_xor_sync(0xFFFFFFFFu, p, 2);
    if ((lane & 3) == 0) {
        int h = lane >> 2;
        float ev = __expf(p * scale);
        scores[(size_t)e * HH + h] = ev;
        atomicAdd(&s[tn * HH + h], ev);
    }
}

__global__ void self_scores_kernel(const float* __restrict__ Q, const float* __restrict__ Kk,
                                   const float* __restrict__ attr,
                                   const int* __restrict__ src, const int* __restrict__ dst,
                                   float* __restrict__ scores, float* __restrict__ s) {
    int e = (blockIdx.x * blockDim.x + threadIdx.x) >> 5;
    int lane = threadIdx.x & 31;
    if (e >= EE) return;
    int sn = src[e], tn = dst[e];
    const float4* q4 = (const float4*)(Q    + (size_t)tn * DD);
    const float4* k4 = (const float4*)(Kk   + (size_t)sn * DD);
    const float4* a4 = (const float4*)(attr + (size_t)e  * DD);
    float4 qa = q4[2 * lane], qb = q4[2 * lane + 1];
    float4 ka = k4[2 * lane], kb = k4[2 * lane + 1];
    float4 aa = a4[2 * lane], ab = a4[2 * lane + 1];
    float p = qa.x * ka.x * aa.x + qa.y * ka.y * aa.y + qa.z * ka.z * aa.z + qa.w * ka.w * aa.w
            + qb.x * kb.x * ab.x + qb.y * kb.y * ab.y + qb.z * kb.z * ab.z + qb.w * kb.w * ab.w;
    p += __shfl_xor_sync(0xFFFFFFFFu, p, 1);
    p += __shfl_xor_sync(0xFFFFFFFFu, p, 2);
    if ((lane & 3) == 0) {
        int h = lane >> 2;
        float ev = __expf(p);   // no 1/sqrt(hd) in SelfMHA
        scores[(size_t)e * HH + h] = ev;
        atomicAdd(&s[tn * HH + h], ev);
    }
}

__global__ void agg_kernel(const float* __restrict__ scores, const float* __restrict__ rsum,
                           const float* __restrict__ V,
                           const int* __restrict__ src, const int* __restrict__ dst,
                           float* __restrict__ agg) {
    int e = (blockIdx.x * blockDim.x + threadIdx.x) >> 5;
    int lane = threadIdx.x & 31;
    if (e >= EE) return;
    int sn = src[e], tn = dst[e];
    int h = lane >> 2;
    float w = scores[(size_t)e * HH + h] * rsum[tn * HH + h];
    const float4* v4 = (const float4*)(V + (size_t)sn * DD);
    float4 va = v4[2 * lane], vb = v4[2 * lane + 1];
    float* dstp = agg + (size_t)tn * DD + lane * 8;
    atomicAdd(dstp + 0, w * va.x);
    atomicAdd(dstp + 1, w * va.y);
    atomicAdd(dstp + 2, w * va.z);
    atomicAdd(dstp + 3, w * va.w);
    atomicAdd(dstp + 4, w * vb.x);
    atomicAdd(dstp + 5, w * vb.y);
    atomicAdd(dstp + 6, w * vb.z);
    atomicAdd(dstp + 7, w * vb.w);
}

// ---------------- residual + RMSNorm: out = rmsnorm(a+b) * g ----------------
__global__ void add_rmsnorm_kernel(const float* __restrict__ a, const float* __restrict__ b,
                                   const float* __restrict__ g, float* __restrict__ out) {
    int row = blockIdx.x;
    int d = threadIdx.x;
    float x = a[(size_t)row * DD + d] + b[(size_t)row * DD + d];
    float v = x * x;
    __shared__ float red[8];
    #pragma unroll
    for (int o = 16; o; o >>= 1) v += __shfl_xor_sync(0xFFFFFFFFu, v, o);
    if ((d & 31) == 0) red[d >> 5] = v;
    __syncthreads();
    if (d < 8) {
        float t = red[d];
        #pragma unroll
        for (int o = 4; o; o >>= 1) t += __shfl_xor_sync(0xFFu, t, o);
        if (d == 0) red[0] = t;
    }
    __syncthreads();
    float norm = sqrtf(red[0]) * 0.0625f;
    float inv = 1.0f / fmaxf(norm, 1e-8f);
    out[(size_t)row * DD + d] = x * inv * g[d];
}

// ---------------- SwiGLU activation -----------------------------------------
__global__ void swiglu_act_kernel(float* __restrict__ h1, const float* __restrict__ h2, int n) {
    int i = blockIdx.x * blockDim.x + threadIdx.x;
    if (i >= n) return;
    float x = h1[i];
    h1[i] = x * (1.0f / (1.0f + __expf(-x))) * h2[i];
}

// ---------------- launch ----------------------------------------------------
static inline dim3 gg128(int M, int Ncols) { return dim3((Ncols + 127) / 128, (M + 127) / 128); }

extern "C" void kernel_launch(void* const* d_in, const int* in_sizes, int n_in,
                              void* d_out, int out_size) {
    const float* root      = (const float*)d_in[0];
    const float* node      = (const float*)d_in[1];
    const float* fringe    = (const float*)d_in[2];
    const int*   ntr_idx   = (const int*)d_in[3];
    const int*   rtr_idx   = (const int*)d_in[4];
    const int*   rtf_idx   = (const int*)d_in[5];
    const float* edge_attr = (const float*)d_in[6];
    const float* ntr_wq    = (const float*)d_in[7];
    const float* ntr_wkv   = (const float*)d_in[8];
    const float* ntr_wout  = (const float*)d_in[9];
    const float* ntr_g     = (const float*)d_in[10];
    const float* rtr_wqkv  = (const float*)d_in[11];
    const float* rtr_wout  = (const float*)d_in[12];
    const float* rtr_g     = (const float*)d_in[13];
    const float* ffn_win   = (const float*)d_in[14];
    const float* ffn_v     = (const float*)d_in[15];
    const float* ffn_wout  = (const float*)d_in[16];
    const float* ffn_g     = (const float*)d_in[17];
    const float* rtf_wq    = (const float*)d_in[18];
    const float* rtf_wkv   = (const float*)d_in[19];
    const float* rtf_wout  = (const float*)d_in[20];
    float* out = (float*)d_out;

    float *q, *k, *v, *kvtmp, *scores, *s, *agg, *x1, *x2, *tmp, *h1, *h2;
    cudaGetSymbolAddress((void**)&q,      g_q);
    cudaGetSymbolAddress((void**)&k,      g_k);
    cudaGetSymbolAddress((void**)&v,      g_v);
    cudaGetSymbolAddress((void**)&kvtmp,  g_kvtmp);
    cudaGetSymbolAddress((void**)&scores, g_scores);
    cudaGetSymbolAddress((void**)&s,      g_s);
    cudaGetSymbolAddress((void**)&agg,    g_agg);
    cudaGetSymbolAddress((void**)&x1,     g_x1);
    cudaGetSymbolAddress((void**)&x2,     g_x2);
    cudaGetSymbolAddress((void**)&tmp,    g_tmp);
    cudaGetSymbolAddress((void**)&h1,     g_h1);
    cudaGetSymbolAddress((void**)&h2,     g_h2);

    const float iscale = 0.17677669529663687f;  // 1/sqrt(32)
    const int edgeBlocks = EE / 8;
    const int resetBlocks = (NN * DD) / 256;
    const int ndBlocks = (NN * DD) / 256;
    const int nhBlocks = (NN * HH) / 256;

    // ===== stage 1: nodes_to_root CrossMHA + residual rmsnorm -> x1 =====
    tgemm_kernel<<<gg128(NN, DD), 256>>>(root, ntr_wq, q, NN, DD, DD);
    tgemm_kernel<<<gg128(NN, 2 * DD), 256>>>(node, ntr_wkv, kvtmp, NN, 2 * DD, DD);
    deint_kv_kernel<<<ndBlocks, 256>>>(kvtmp, k, v);
    reset_kernel<<<resetBlocks, 256>>>(s, agg);
    cross_scores_kernel<<<edgeBlocks, 256>>>(q, k, ntr_idx, ntr_idx + EE, scores, s, iscale);
    rcp_kernel<<<nhBlocks, 256>>>(s);
    agg_kernel<<<edgeBlocks, 256>>>(scores, s, v, ntr_idx, ntr_idx + EE, agg);
    tgemm_kernel<<<gg128(NN, DD), 256>>>(agg, ntr_wout, tmp, NN, DD, DD);
    add_rmsnorm_kernel<<<NN, 256>>>(root, tmp, ntr_g, x1);

    // ===== stage 2: roots_to_root SelfMHA + residual rmsnorm -> x2 =====
    tgemm_kernel<<<gg128(NN, 3 * DD), 256>>>(x1, rtr_wqkv, kvtmp, NN, 3 * DD, DD);
    deint_qkv_kernel<<<ndBlocks, 256>>>(kvtmp, q, k, v);
    reset_kernel<<<resetBlocks, 256>>>(s, agg);
    self_scores_kernel<<<edgeBlocks, 256>>>(q, k, edge_attr, rtr_idx, rtr_idx + EE, scores, s);
    rcp_kernel<<<nhBlocks, 256>>>(s);
    agg_kernel<<<edgeBlocks, 256>>>(scores, s, v, rtr_idx, rtr_idx + EE, agg);
    tgemm_kernel<<<gg128(NN, DD), 256>>>(agg, rtr_wout, tmp, NN, DD, DD);
    add_rmsnorm_kernel<<<NN, 256>>>(x1, tmp, rtr_g, x2);

    // ===== stage 3: SwiGLU FFN (on root_features) + residual rmsnorm -> out =====
    tgemm_kernel<<<gg128(NN, IM), 256>>>(root, ffn_win, h1, NN, IM, DD);
    tgemm_kernel<<<gg128(NN, IM), 256>>>(root, ffn_v, h2, NN, IM, DD);
    swiglu_act_kernel<<<(NN * IM + 255) / 256, 256>>>(h1, h2, NN * IM);
    tgemm_kernel<<<gg128(NN, DD), 256>>>(h1, ffn_wout, tmp, NN, DD, IM);
    add_rmsnorm_kernel<<<NN, 256>>>(tmp, x2, ffn_g, out);

    // ===== stage 4: root_to_fringe CrossMHA -> out[N*D : 2*N*D] =====
    tgemm_kernel<<<gg128(NN, DD), 256>>>(fringe, rtf_wq, q, NN, DD, DD);
    tgemm_kernel<<<gg128(NN, 2 * DD), 256>>>(root, rtf_wkv, kvtmp, NN, 2 * DD, DD);
    deint_kv_kernel<<<ndBlocks, 256>>>(kvtmp, k, v);
    reset_kernel<<<resetBlocks, 256>>>(s, agg);
    cross_scores_kernel<<<edgeBlocks, 256>>>(q, k, rtf_idx, rtf_idx + EE, scores, s, iscale);
    rcp_kernel<<<nhBlocks, 256>>>(s);
    agg_kernel<<<edgeBlocks, 256>>>(scores, s, v, rtf_idx, rtf_idx + EE, agg);
    tgemm_kernel<<<gg128(NN, DD), 256>>>(agg, rtf_wout, out + (size_t)NN * DD, NN, DD, DD);
}

// round 7
// speedup vs baseline: 1.2859x; 1.2859x over previous
#include <cuda_runtime.h>
#include <math.h>
#include <stdint.h>

// Problem constants (fixed by the dataset)
#define NN 16384      // nodes per set
#define DD 256        // model dim
#define EE 131072     // edges per relation
#define HH 8          // heads
#define HDIM 32       // head dim
#define IM 682        // SwiGLU intermediate

// ---------------- scratch (static device globals; no allocations) ----------
__device__ float g_q[NN * DD];          // 16 MB
__device__ float g_kv[NN * 3 * DD];     // 48 MB (kv 2D or qkv 3D)
__device__ float g_scores[EE * HH];     // 4 MB
__device__ float g_s[NN * HH];
__device__ float g_agg[NN * DD];        // 16 MB
__device__ float g_x1[NN * DD];
__device__ float g_x2[NN * DD];
__device__ float g_tmp[NN * DD];
__device__ float g_h1[NN * IM];         // 44.7 MB
__device__ float g_h2[NN * IM];         // 44.7 MB

__device__ __forceinline__ uint32_t f2tf32(float f) {
    uint32_t r;
    asm("cvt.rna.tf32.f32 %0, %1;" : "=r"(r) : "f"(f));
    return r;
}

// ---------------- TF32 tensor-core GEMM (proven 1368-config version) --------
// C[M,N] = A[M,K] @ B[K,N], row-major fp32 in/out, tf32 mma.sync compute.
// 128x128 block tile, BK=32, 256 threads (8 warps), warp tile 64x32.
#define BM 128
#define BN 128
#define BK 32
#define PAD 132   // padded row length (floats) for conflict-free frag loads

__global__ __launch_bounds__(256)
void tgemm_kernel(const float* __restrict__ A, const float* __restrict__ B,
                  float* __restrict__ C, int M, int N, int K) {
    __shared__ uint32_t As[BK][PAD];   // As[k][m], tf32 bits
    __shared__ uint32_t Bs[BK][PAD];   // Bs[k][n], tf32 bits

    const int tid  = threadIdx.x;
    const int lane = tid & 31;
    const int wid  = tid >> 5;            // 0..7
    const int warpM = wid & 1;            // 2 warps along M
    const int warpN = wid >> 1;           // 4 warps along N
    const int g   = lane >> 2;            // groupID 0..7
    const int tig = lane & 3;             // thread-in-group 0..3

    const int rowBase = blockIdx.y * BM;
    const int colBase = blockIdx.x * BN;

    float acc[4][4][4];
    #pragma unroll
    for (int i = 0; i < 4; i++)
        #pragma unroll
        for (int j = 0; j < 4; j++)
            #pragma unroll
            for (int r = 0; r < 4; r++) acc[i][j][r] = 0.0f;

    for (int k0 = 0; k0 < K; k0 += BK) {
        __syncthreads();
        // ---- load A tile: BM x BK, transposed into As[k][m], float2 global loads
        #pragma unroll
        for (int i = 0; i < 8; i++) {
            int l  = tid + i * 256;       // 0..2047 float2 slots
            int r  = l >> 4;              // 0..127
            int c2 = l & 15;              // 0..15 -> k pair
            int gr = rowBase + r;
            int gk = k0 + 2 * c2;
            float2 v = make_float2(0.0f, 0.0f);
            if (gr < M && gk < K) v = *(const float2*)(A + (size_t)gr * K + gk);
            As[2 * c2][r]     = f2tf32(v.x);
            As[2 * c2 + 1][r] = f2tf32(v.y);
        }
        // ---- load B tile: BK x BN into Bs[k][n], float2 global loads
        #pragma unroll
        for (int i = 0; i < 8; i++) {
            int l  = tid + i * 256;
            int kk = l >> 6;              // 0..31
            int c2 = l & 63;              // 0..63 -> n pair
            int gk = k0 + kk;
            int gc = colBase + 2 * c2;
            float2 v = make_float2(0.0f, 0.0f);
            if (gk < K && gc < N) v = *(const float2*)(B + (size_t)gk * N + gc);
            Bs[kk][2 * c2]     = f2tf32(v.x);
            Bs[kk][2 * c2 + 1] = f2tf32(v.y);
        }
        __syncthreads();

        // ---- compute: 4 k-atoms of 8
        #pragma unroll
        for (int ka = 0; ka < 4; ka++) {
            const int kb = ka * 8;
            uint32_t a[4][4], b[4][2];
            #pragma unroll
            for (int ma = 0; ma < 4; ma++) {
                int m0 = warpM * 64 + ma * 16;
                a[ma][0] = As[kb + tig][m0 + g];
                a[ma][1] = As[kb + tig][m0 + g + 8];
                a[ma][2] = As[kb + tig + 4][m0 + g];
                a[ma][3] = As[kb + tig + 4][m0 + g + 8];
            }
            #pragma unroll
            for (int na = 0; na < 4; na++) {
                int n0 = warpN * 32 + na * 8;
                b[na][0] = Bs[kb + tig][n0 + g];
                b[na][1] = Bs[kb + tig + 4][n0 + g];
            }
            #pragma unroll
            for (int ma = 0; ma < 4; ma++)
                #pragma unroll
                for (int na = 0; na < 4; na++) {
                    asm volatile(
                        "mma.sync.aligned.m16n8k8.row.col.f32.tf32.tf32.f32 "
                        "{%0,%1,%2,%3}, {%4,%5,%6,%7}, {%8,%9}, {%0,%1,%2,%3};\n"
                        : "+f"(acc[ma][na][0]), "+f"(acc[ma][na][1]),
                          "+f"(acc[ma][na][2]), "+f"(acc[ma][na][3])
                        : "r"(a[ma][0]), "r"(a[ma][1]), "r"(a[ma][2]), "r"(a[ma][3]),
                          "r"(b[na][0]), "r"(b[na][1]));
                }
        }
    }

    // ---- store C (float2 per row-half of each atom); N even -> alignment OK
    #pragma unroll
    for (int ma = 0; ma < 4; ma++) {
        int r0 = rowBase + warpM * 64 + ma * 16 + g;
        #pragma unroll
        for (int na = 0; na < 4; na++) {
            int c = colBase + warpN * 32 + na * 8 + tig * 2;
            if (c < N) {
                if (r0 < M)
                    *(float2*)(C + (size_t)r0 * N + c) = make_float2(acc[ma][na][0], acc[ma][na][1]);
                if (r0 + 8 < M)
                    *(float2*)(C + (size_t)(r0 + 8) * N + c) = make_float2(acc[ma][na][2], acc[ma][na][3]);
            }
        }
    }
}

// ---------------- reset: agg=0, s=0 -----------------------------------------
__global__ void reset_kernel(float* s, float* agg) {
    int i = blockIdx.x * blockDim.x + threadIdx.x;   // N*D threads
    agg[i] = 0.0f;
    if (i < NN * HH) s[i] = 0.0f;
}

// ---------------- reciprocal of softmax denominators ------------------------
__global__ void rcp_kernel(float* __restrict__ s) {
    int i = blockIdx.x * blockDim.x + threadIdx.x;   // NN*HH threads
    if (i < NN * HH) s[i] = __frcp_rn(s[i]);
}

// ---------------- cross-MHA edge kernels (interleaved kv, proven layout) ----
// KV layout per node: kv[i*512 + h*64 + 2*d + {0:k,1:v}]
// No max-subtraction: scores are O(10), exp safe in fp32; softmax is
// shift-invariant so the result matches the reference.
__global__ void cross_scores_kernel(const float* __restrict__ Q, const float* __restrict__ KV,
                                    const int* __restrict__ src, const int* __restrict__ dst,
                                    float* __restrict__ scores, float* __restrict__ s,
                                    float scale) {
    int warp = (blockIdx.x * blockDim.x + threadIdx.x) >> 5;
    int lane = threadIdx.x & 31;
    if (warp >= EE) return;
    int sn = src[warp], tn = dst[warp];
    const float* q  = Q  + (size_t)tn * DD;
    const float* kv = KV + (size_t)sn * (2 * DD);
    #pragma unroll
    for (int h = 0; h < HH; h++) {
        float p = q[h * HDIM + lane] * kv[h * 64 + 2 * lane];
        #pragma unroll
        for (int o = 16; o; o >>= 1) p += __shfl_xor_sync(0xFFFFFFFFu, p, o);
        if (lane == 0) {
            float ev = __expf(p * scale);
            scores[(size_t)warp * HH + h] = ev;
            atomicAdd(&s[tn * HH + h], ev);
        }
    }
}

__global__ void cross_agg_kernel(const float* __restrict__ scores, const float* __restrict__ rsum,
                                 const float* __restrict__ KV,
                                 const int* __restrict__ src, const int* __restrict__ dst,
                                 float* __restrict__ agg) {
    int warp = (blockIdx.x * blockDim.x + threadIdx.x) >> 5;
    int lane = threadIdx.x & 31;
    if (warp >= EE) return;
    int sn = src[warp], tn = dst[warp];
    const float* kv = KV + (size_t)sn * (2 * DD);
    #pragma unroll
    for (int h = 0; h < HH; h++) {
        float w = scores[(size_t)warp * HH + h] * rsum[tn * HH + h];
        float v = kv[h * 64 + 2 * lane + 1];
        atomicAdd(&agg[(size_t)tn * DD + h * HDIM + lane], w * v);
    }
}

// ---------------- self-MHA edge kernels -------------------------------------
// QKV layout per node: qkv[i*768 + h*96 + 3*d + {0:q,1:k,2:v}]
__global__ void self_scores_kernel(const float* __restrict__ QKV, const float* __restrict__ attr,
                                   const int* __restrict__ src, const int* __restrict__ dst,
                                   float* __restrict__ scores, float* __restrict__ s) {
    int warp = (blockIdx.x * blockDim.x + threadIdx.x) >> 5;
    int lane = threadIdx.x & 31;
    if (warp >= EE) return;
    int sn = src[warp], tn = dst[warp];
    const float* qd = QKV + (size_t)tn * (3 * DD);
    const float* ks = QKV + (size_t)sn * (3 * DD);
    const float* ea = attr + (size_t)warp * DD;   // [H, HD] per edge
    #pragma unroll
    for (int h = 0; h < HH; h++) {
        float p = qd[h * 96 + 3 * lane] * ks[h * 96 + 3 * lane + 1] * ea[h * HDIM + lane];
        #pragma unroll
        for (int o = 16; o; o >>= 1) p += __shfl_xor_sync(0xFFFFFFFFu, p, o);
        if (lane == 0) {
            float ev = __expf(p);   // no 1/sqrt(hd) in SelfMHA
            scores[(size_t)warp * HH + h] = ev;
            atomicAdd(&s[tn * HH + h], ev);
        }
    }
}

__global__ void self_agg_kernel(const float* __restrict__ scores, const float* __restrict__ rsum,
                                const float* __restrict__ QKV,
                                const int* __restrict__ src, const int* __restrict__ dst,
                                float* __restrict__ agg) {
    int warp = (blockIdx.x * blockDim.x + threadIdx.x) >> 5;
    int lane = threadIdx.x & 31;
    if (warp >= EE) return;
    int sn = src[warp], tn = dst[warp];
    const float* vs = QKV + (size_t)sn * (3 * DD);
    #pragma unroll
    for (int h = 0; h < HH; h++) {
        float w = scores[(size_t)warp * HH + h] * rsum[tn * HH + h];
        float v = vs[h * 96 + 3 * lane + 2];
        atomicAdd(&agg[(size_t)tn * DD + h * HDIM + lane], w * v);
    }
}

// ---------------- residual + RMSNorm: out = rmsnorm(a+b) * g ----------------
__global__ void add_rmsnorm_kernel(const float* __restrict__ a, const float* __restrict__ b,
                                   const float* __restrict__ g, float* __restrict__ out) {
    int row = blockIdx.x;
    int d = threadIdx.x;   // 256 threads, D = 256
    float x = a[(size_t)row * DD + d] + b[(size_t)row * DD + d];
    float v = x * x;
    __shared__ float red[8];
    #pragma unroll
    for (int o = 16; o; o >>= 1) v += __shfl_xor_sync(0xFFFFFFFFu, v, o);
    if ((d & 31) == 0) red[d >> 5] = v;
    __syncthreads();
    if (d < 8) {
        float t = red[d];
        #pragma unroll
        for (int o = 4; o; o >>= 1) t += __shfl_xor_sync(0xFFu, t, o);
        if (d == 0) red[0] = t;
    }
    __syncthreads();
    float norm = sqrtf(red[0]) * 0.0625f;          // * D^-0.5 = /16
    float inv = 1.0f / fmaxf(norm, 1e-8f);
    out[(size_t)row * DD + d] = x * inv * g[d];
}

// ---------------- SwiGLU activation: h1 = h1*sigmoid(h1)*h2 -----------------
__global__ void swiglu_act_kernel(float* __restrict__ h1, const float* __restrict__ h2, int n) {
    int i = blockIdx.x * blockDim.x + threadIdx.x;
    if (i >= n) return;
    float x = h1[i];
    h1[i] = x * (1.0f / (1.0f + __expf(-x))) * h2[i];
}

// ---------------- launch ----------------------------------------------------
static inline dim3 gg128(int M, int Ncols) { return dim3((Ncols + 127) / 128, (M + 127) / 128); }

extern "C" void kernel_launch(void* const* d_in, const int* in_sizes, int n_in,
                              void* d_out, int out_size) {
    const float* root      = (const float*)d_in[0];
    const float* node      = (const float*)d_in[1];
    const float* fringe    = (const float*)d_in[2];
    const int*   ntr_idx   = (const int*)d_in[3];     // [2,E]: src row then dst row
    const int*   rtr_idx   = (const int*)d_in[4];
    const int*   rtf_idx   = (const int*)d_in[5];
    const float* edge_attr = (const float*)d_in[6];
    const float* ntr_wq    = (const float*)d_in[7];
    const float* ntr_wkv   = (const float*)d_in[8];
    const float* ntr_wout  = (const float*)d_in[9];
    const float* ntr_g     = (const float*)d_in[10];
    const float* rtr_wqkv  = (const float*)d_in[11];
    const float* rtr_wout  = (const float*)d_in[12];
    const float* rtr_g     = (const float*)d_in[13];
    const float* ffn_win   = (const float*)d_in[14];
    const float* ffn_v     = (const float*)d_in[15];
    const float* ffn_wout  = (const float*)d_in[16];
    const float* ffn_g     = (const float*)d_in[17];
    const float* rtf_wq    = (const float*)d_in[18];
    const float* rtf_wkv   = (const float*)d_in[19];
    const float* rtf_wout  = (const float*)d_in[20];
    float* out = (float*)d_out;

    float *q, *kv, *scores, *s, *agg, *x1, *x2, *tmp, *h1, *h2;
    cudaGetSymbolAddress((void**)&q,      g_q);
    cudaGetSymbolAddress((void**)&kv,     g_kv);
    cudaGetSymbolAddress((void**)&scores, g_scores);
    cudaGetSymbolAddress((void**)&s,      g_s);
    cudaGetSymbolAddress((void**)&agg,    g_agg);
    cudaGetSymbolAddress((void**)&x1,     g_x1);
    cudaGetSymbolAddress((void**)&x2,     g_x2);
    cudaGetSymbolAddress((void**)&tmp,    g_tmp);
    cudaGetSymbolAddress((void**)&h1,     g_h1);
    cudaGetSymbolAddress((void**)&h2,     g_h2);

    const float iscale = 0.17677669529663687f;  // 1/sqrt(32)
    const int edgeBlocks = EE / 8;              // 8 warps/block
    const int resetBlocks = (NN * DD) / 256;
    const int nhBlocks   = (NN * HH) / 256;

    // ===== stage 1: nodes_to_root CrossMHA + residual rmsnorm -> x1 =====
    tgemm_kernel<<<gg128(NN, DD), 256>>>(root, ntr_wq, q, NN, DD, DD);
    tgemm_kernel<<<gg128(NN, 2 * DD), 256>>>(node, ntr_wkv, kv, NN, 2 * DD, DD);
    reset_kernel<<<resetBlocks, 256>>>(s, agg);
    cross_scores_kernel<<<edgeBlocks, 256>>>(q, kv, ntr_idx, ntr_idx + EE, scores, s, iscale);
    rcp_kernel<<<nhBlocks, 256>>>(s);
    cross_agg_kernel<<<edgeBlocks, 256>>>(scores, s, kv, ntr_idx, ntr_idx + EE, agg);
    tgemm_kernel<<<gg128(NN, DD), 256>>>(agg, ntr_wout, tmp, NN, DD, DD);
    add_rmsnorm_kernel<<<NN, 256>>>(root, tmp, ntr_g, x1);

    // ===== stage 2: roots_to_root SelfMHA + residual rmsnorm -> x2 =====
    tgemm_kernel<<<gg128(NN, 3 * DD), 256>>>(x1, rtr_wqkv, kv, NN, 3 * DD, DD);
    reset_kernel<<<resetBlocks, 256>>>(s, agg);
    self_scores_kernel<<<edgeBlocks, 256>>>(kv, edge_attr, rtr_idx, rtr_idx + EE, scores, s);
    rcp_kernel<<<nhBlocks, 256>>>(s);
    self_agg_kernel<<<edgeBlocks, 256>>>(scores, s, kv, rtr_idx, rtr_idx + EE, agg);
    tgemm_kernel<<<gg128(NN, DD), 256>>>(agg, rtr_wout, tmp, NN, DD, DD);
    add_rmsnorm_kernel<<<NN, 256>>>(x1, tmp, rtr_g, x2);

    // ===== stage 3: SwiGLU FFN (on root_features) + residual rmsnorm -> out =====
    tgemm_kernel<<<gg128(NN, IM), 256>>>(root, ffn_win, h1, NN, IM, DD);
    tgemm_kernel<<<gg128(NN, IM), 256>>>(root, ffn_v, h2, NN, IM, DD);
    swiglu_act_kernel<<<(NN * IM + 255) / 256, 256>>>(h1, h2, NN * IM);
    tgemm_kernel<<<gg128(NN, DD), 256>>>(h1, ffn_wout, tmp, NN, DD, IM);
    add_rmsnorm_kernel<<<NN, 256>>>(tmp, x2, ffn_g, out);

    // ===== stage 4: root_to_fringe CrossMHA -> out[N*D : 2*N*D] =====
    tgemm_kernel<<<gg128(NN, DD), 256>>>(fringe, rtf_wq, q, NN, DD, DD);
    tgemm_kernel<<<gg128(NN, 2 * DD), 256>>>(root, rtf_wkv, kv, NN, 2 * DD, DD);
    reset_kernel<<<resetBlocks, 256>>>(s, agg);
    cross_scores_kernel<<<edgeBlocks, 256>>>(q, kv, rtf_idx, rtf_idx + EE, scores, s, iscale);
    rcp_kernel<<<nhBlocks, 256>>>(s);
    cross_agg_kernel<<<edgeBlocks, 256>>>(scores, s, kv, rtf_idx, rtf_idx + EE, agg);
    tgemm_kernel<<<gg128(NN, DD), 256>>>(agg, rtf_wout, out + (size_t)NN * DD, NN, DD, DD);
}

// round 8
// speedup vs baseline: 1.6519x; 1.2847x over previous
#include <cuda_runtime.h>
#include <math.h>
#include <stdint.h>

// Problem constants (fixed by the dataset)
#define NN 16384      // nodes per set
#define DD 256        // model dim
#define EE 131072     // edges per relation
#define HH 8          // heads
#define HDIM 32       // head dim
#define IM 682        // SwiGLU intermediate

// ---------------- scratch (static device globals; no allocations) ----------
__device__ float g_q[NN * DD];          // q (contiguous [n][h*32+d])
__device__ float g_k[NN * DD];          // k
__device__ float g_v[NN * DD];          // v
__device__ float g_kvtmp[NN * 3 * DD];  // raw interleaved kv / qkv GEMM output
__device__ float g_scores[EE * HH];
__device__ float g_s[NN * HH];
__device__ float g_agg[NN * DD];
__device__ float g_x1[NN * DD];
__device__ float g_x2[NN * DD];
__device__ float g_tmp[NN * DD];
__device__ float g_h1[NN * IM];
__device__ float g_h2[NN * IM];

__device__ __forceinline__ uint32_t f2tf32(float f) {
    uint32_t r;
    asm("cvt.rna.tf32.f32 %0, %1;" : "=r"(r) : "f"(f));
    return r;
}

// ---------------- TF32 tensor-core GEMM with register prefetch --------------
// C[M,N] = A[M,K] @ B[K,N], row-major fp32 in/out, tf32 mma.sync compute.
// 128x128 block tile, BK=32, 256 threads (8 warps), warp tile 64x32.
// Software pipeline: LDG of tile t+1 overlaps MMA compute of tile t.
#define BM 128
#define BN 128
#define BK 32
#define PAD 132   // padded row length (floats), proven conflict pattern

__global__ __launch_bounds__(256)
void tgemm_kernel(const float* __restrict__ A, const float* __restrict__ B,
                  float* __restrict__ C, int M, int N, int K) {
    __shared__ uint32_t As[BK][PAD];   // As[k][m], tf32 bits
    __shared__ uint32_t Bs[BK][PAD];   // Bs[k][n], tf32 bits

    const int tid  = threadIdx.x;
    const int lane = tid & 31;
    const int wid  = tid >> 5;            // 0..7
    const int warpM = wid & 1;            // 2 warps along M
    const int warpN = wid >> 1;           // 4 warps along N
    const int g   = lane >> 2;            // groupID 0..7
    const int tig = lane & 3;             // thread-in-group 0..3

    const int rowBase = blockIdx.y * BM;
    const int colBase = blockIdx.x * BN;

    float acc[4][4][4];
    #pragma unroll
    for (int i = 0; i < 4; i++)
        #pragma unroll
        for (int j = 0; j < 4; j++)
            #pragma unroll
            for (int r = 0; r < 4; r++) acc[i][j][r] = 0.0f;

    float2 aReg[8], bReg[8];
    const int T = (K + BK - 1) / BK;

    // ---- prologue: load tile 0 into registers
    #pragma unroll
    for (int i = 0; i < 8; i++) {
        int l  = tid + i * 256;
        int r  = l >> 4;
        int c2 = l & 15;
        int gr = rowBase + r, gk = 2 * c2;
        aReg[i] = (gr < M && gk < K) ? *(const float2*)(A + (size_t)gr * K + gk)
                                     : make_float2(0.0f, 0.0f);
    }
    #pragma unroll
    for (int i = 0; i < 8; i++) {
        int l  = tid + i * 256;
        int kk = l >> 6;
        int c2 = l & 63;
        int gk = kk, gc = colBase + 2 * c2;
        bReg[i] = (gk < K && gc < N) ? *(const float2*)(B + (size_t)gk * N + gc)
                                     : make_float2(0.0f, 0.0f);
    }

    for (int t = 0; t < T; t++) {
        // ---- store current registers into smem (with tf32 convert)
        #pragma unroll
        for (int i = 0; i < 8; i++) {
            int l  = tid + i * 256;
            int r  = l >> 4;
            int c2 = l & 15;
            As[2 * c2][r]     = f2tf32(aReg[i].x);
            As[2 * c2 + 1][r] = f2tf32(aReg[i].y);
        }
        #pragma unroll
        for (int i = 0; i < 8; i++) {
            int l  = tid + i * 256;
            int kk = l >> 6;
            int c2 = l & 63;
            Bs[kk][2 * c2]     = f2tf32(bReg[i].x);
            Bs[kk][2 * c2 + 1] = f2tf32(bReg[i].y);
        }
        __syncthreads();

        // ---- prefetch next tile into registers (overlaps compute below)
        if (t + 1 < T) {
            int k0 = (t + 1) * BK;
            #pragma unroll
            for (int i = 0; i < 8; i++) {
                int l  = tid + i * 256;
                int r  = l >> 4;
                int c2 = l & 15;
                int gr = rowBase + r, gk = k0 + 2 * c2;
                aReg[i] = (gr < M && gk < K) ? *(const float2*)(A + (size_t)gr * K + gk)
                                             : make_float2(0.0f, 0.0f);
            }
            #pragma unroll
            for (int i = 0; i < 8; i++) {
                int l  = tid + i * 256;
                int kk = l >> 6;
                int c2 = l & 63;
                int gk = k0 + kk, gc = colBase + 2 * c2;
                bReg[i] = (gk < K && gc < N) ? *(const float2*)(B + (size_t)gk * N + gc)
                                             : make_float2(0.0f, 0.0f);
            }
        }

        // ---- compute: 4 k-atoms of 8
        #pragma unroll
        for (int ka = 0; ka < 4; ka++) {
            const int kb = ka * 8;
            uint32_t a[4][4], b[4][2];
            #pragma unroll
            for (int ma = 0; ma < 4; ma++) {
                int m0 = warpM * 64 + ma * 16;
                a[ma][0] = As[kb + tig][m0 + g];
                a[ma][1] = As[kb + tig][m0 + g + 8];
                a[ma][2] = As[kb + tig + 4][m0 + g];
                a[ma][3] = As[kb + tig + 4][m0 + g + 8];
            }
            #pragma unroll
            for (int na = 0; na < 4; na++) {
                int n0 = warpN * 32 + na * 8;
                b[na][0] = Bs[kb + tig][n0 + g];
                b[na][1] = Bs[kb + tig + 4][n0 + g];
            }
            #pragma unroll
            for (int ma = 0; ma < 4; ma++)
                #pragma unroll
                for (int na = 0; na < 4; na++) {
                    asm volatile(
                        "mma.sync.aligned.m16n8k8.row.col.f32.tf32.tf32.f32 "
                        "{%0,%1,%2,%3}, {%4,%5,%6,%7}, {%8,%9}, {%0,%1,%2,%3};\n"
                        : "+f"(acc[ma][na][0]), "+f"(acc[ma][na][1]),
                          "+f"(acc[ma][na][2]), "+f"(acc[ma][na][3])
                        : "r"(a[ma][0]), "r"(a[ma][1]), "r"(a[ma][2]), "r"(a[ma][3]),
                          "r"(b[na][0]), "r"(b[na][1]));
                }
        }
        __syncthreads();   // all reads done before next STS overwrites
    }

    // ---- store C (float2 per row-half of each atom); N even -> alignment OK
    #pragma unroll
    for (int ma = 0; ma < 4; ma++) {
        int r0 = rowBase + warpM * 64 + ma * 16 + g;
        #pragma unroll
        for (int na = 0; na < 4; na++) {
            int c = colBase + warpN * 32 + na * 8 + tig * 2;
            if (c < N) {
                if (r0 < M)
                    *(float2*)(C + (size_t)r0 * N + c) = make_float2(acc[ma][na][0], acc[ma][na][1]);
                if (r0 + 8 < M)
                    *(float2*)(C + (size_t)(r0 + 8) * N + c) = make_float2(acc[ma][na][2], acc[ma][na][3]);
            }
        }
    }
}

// ---------------- de-interleave kernels -------------------------------------
// kv [n][h*64 + 2d + {0:k,1:v}] -> k[n][h*32+d], v[n][h*32+d]
__global__ void deint_kv_kernel(const float* __restrict__ kv,
                                float* __restrict__ k, float* __restrict__ v) {
    int i = blockIdx.x * blockDim.x + threadIdx.x;   // NN*DD threads
    int n = i >> 8, j = i & 255;
    int h = j >> 5, d = j & 31;
    float2 p = *(const float2*)(kv + (size_t)n * 512 + h * 64 + 2 * d);
    k[i] = p.x;
    v[i] = p.y;
}

// qkv [n][h*96 + 3d + {0:q,1:k,2:v}] -> q,k,v [n][h*32+d]
__global__ void deint_qkv_kernel(const float* __restrict__ qkv,
                                 float* __restrict__ q, float* __restrict__ k,
                                 float* __restrict__ v) {
    int i = blockIdx.x * blockDim.x + threadIdx.x;   // NN*DD threads
    int n = i >> 8, j = i & 255;
    int h = j >> 5, d = j & 31;
    const float* p = qkv + (size_t)n * 768 + h * 96 + 3 * d;
    q[i] = p[0];
    k[i] = p[1];
    v[i] = p[2];
}

// ---------------- reset: agg=0, s=0 -----------------------------------------
__global__ void reset_kernel(float* s, float* agg) {
    int i = blockIdx.x * blockDim.x + threadIdx.x;   // NN*DD threads
    agg[i] = 0.0f;
    if (i < NN * HH) s[i] = 0.0f;
}

// ---------------- reciprocal of softmax denominators ------------------------
__global__ void rcp_kernel(float* __restrict__ s) {
    int i = blockIdx.x * blockDim.x + threadIdx.x;
    if (i < NN * HH) s[i] = __frcp_rn(s[i]);
}

// ---------------- edge kernels (contiguous [n][h*32+d] layouts) -------------
// Scores: warp per edge; 4 lanes per head; lane handles 8 consecutive dims.
// No max-subtraction: scores are O(10), exp safe in fp32; softmax is
// shift-invariant so the result matches the reference.
__global__ void cross_scores_kernel(const float* __restrict__ Q, const float* __restrict__ Kk,
                                    const int* __restrict__ src, const int* __restrict__ dst,
                                    float* __restrict__ scores, float* __restrict__ s,
                                    float scale) {
    int e = (blockIdx.x * blockDim.x + threadIdx.x) >> 5;
    int lane = threadIdx.x & 31;
    if (e >= EE) return;
    int sn = src[e], tn = dst[e];
    const float4* q4 = (const float4*)(Q  + (size_t)tn * DD);
    const float4* k4 = (const float4*)(Kk + (size_t)sn * DD);
    float4 qa = q4[2 * lane], qb = q4[2 * lane + 1];
    float4 ka = k4[2 * lane], kb = k4[2 * lane + 1];
    float p = qa.x * ka.x + qa.y * ka.y + qa.z * ka.z + qa.w * ka.w
            + qb.x * kb.x + qb.y * kb.y + qb.z * kb.z + qb.w * kb.w;
    p += __shfl_xor_sync(0xFFFFFFFFu, p, 1);
    p += __shfl_xor_sync(0xFFFFFFFFu, p, 2);
    if ((lane & 3) == 0) {
        int h = lane >> 2;
        float ev = __expf(p * scale);
        scores[(size_t)e * HH + h] = ev;
        atomicAdd(&s[tn * HH + h], ev);
    }
}

__global__ void self_scores_kernel(const float* __restrict__ Q, const float* __restrict__ Kk,
                                   const float* __restrict__ attr,
                                   const int* __restrict__ src, const int* __restrict__ dst,
                                   float* __restrict__ scores, float* __restrict__ s) {
    int e = (blockIdx.x * blockDim.x + threadIdx.x) >> 5;
    int lane = threadIdx.x & 31;
    if (e >= EE) return;
    int sn = src[e], tn = dst[e];
    const float4* q4 = (const float4*)(Q    + (size_t)tn * DD);
    const float4* k4 = (const float4*)(Kk   + (size_t)sn * DD);
    const float4* a4 = (const float4*)(attr + (size_t)e  * DD);
    float4 qa = q4[2 * lane], qb = q4[2 * lane + 1];
    float4 ka = k4[2 * lane], kb = k4[2 * lane + 1];
    float4 aa = a4[2 * lane], ab = a4[2 * lane + 1];
    float p = qa.x * ka.x * aa.x + qa.y * ka.y * aa.y + qa.z * ka.z * aa.z + qa.w * ka.w * aa.w
            + qb.x * kb.x * ab.x + qb.y * kb.y * ab.y + qb.z * kb.z * ab.z + qb.w * kb.w * ab.w;
    p += __shfl_xor_sync(0xFFFFFFFFu, p, 1);
    p += __shfl_xor_sync(0xFFFFFFFFu, p, 2);
    if ((lane & 3) == 0) {
        int h = lane >> 2;
        float ev = __expf(p);   // no 1/sqrt(hd) in SelfMHA
        scores[(size_t)e * HH + h] = ev;
        atomicAdd(&s[tn * HH + h], ev);
    }
}

// Agg: warp per edge, loop over heads; each atomic instruction's 32 lanes are
// CONTIGUOUS (h*32+lane) -> 1-2 cache lines per instruction (this is the fix
// for the R6 regression where lanes spanned 8 lines per instruction).
__global__ void agg_kernel(const float* __restrict__ scores, const float* __restrict__ rsum,
                           const float* __restrict__ V,
                           const int* __restrict__ src, const int* __restrict__ dst,
                           float* __restrict__ agg) {
    int e = (blockIdx.x * blockDim.x + threadIdx.x) >> 5;
    int lane = threadIdx.x & 31;
    if (e >= EE) return;
    int sn = src[e], tn = dst[e];
    const float* vp = V   + (size_t)sn * DD;
    float*       ap = agg + (size_t)tn * DD;
    const float* sp = scores + (size_t)e * HH;
    const float* rp = rsum + tn * HH;
    #pragma unroll
    for (int h = 0; h < HH; h++) {
        float w = sp[h] * rp[h];
        atomicAdd(ap + h * HDIM + lane, w * vp[h * HDIM + lane]);
    }
}

// ---------------- residual + RMSNorm: out = rmsnorm(a+b) * g ----------------
__global__ void add_rmsnorm_kernel(const float* __restrict__ a, const float* __restrict__ b,
                                   const float* __restrict__ g, float* __restrict__ out) {
    int row = blockIdx.x;
    int d = threadIdx.x;
    float x = a[(size_t)row * DD + d] + b[(size_t)row * DD + d];
    float v = x * x;
    __shared__ float red[8];
    #pragma unroll
    for (int o = 16; o; o >>= 1) v += __shfl_xor_sync(0xFFFFFFFFu, v, o);
    if ((d & 31) == 0) red[d >> 5] = v;
    __syncthreads();
    if (d < 8) {
        float t = red[d];
        #pragma unroll
        for (int o = 4; o; o >>= 1) t += __shfl_xor_sync(0xFFu, t, o);
        if (d == 0) red[0] = t;
    }
    __syncthreads();
    float norm = sqrtf(red[0]) * 0.0625f;
    float inv = 1.0f / fmaxf(norm, 1e-8f);
    out[(size_t)row * DD + d] = x * inv * g[d];
}

// ---------------- SwiGLU activation -----------------------------------------
__global__ void swiglu_act_kernel(float* __restrict__ h1, const float* __restrict__ h2, int n) {
    int i = blockIdx.x * blockDim.x + threadIdx.x;
    if (i >= n) return;
    float x = h1[i];
    h1[i] = x * (1.0f / (1.0f + __expf(-x))) * h2[i];
}

// ---------------- launch ----------------------------------------------------
static inline dim3 gg128(int M, int Ncols) { return dim3((Ncols + 127) / 128, (M + 127) / 128); }

extern "C" void kernel_launch(void* const* d_in, const int* in_sizes, int n_in,
                              void* d_out, int out_size) {
    const float* root      = (const float*)d_in[0];
    const float* node      = (const float*)d_in[1];
    const float* fringe    = (const float*)d_in[2];
    const int*   ntr_idx   = (const int*)d_in[3];
    const int*   rtr_idx   = (const int*)d_in[4];
    const int*   rtf_idx   = (const int*)d_in[5];
    const float* edge_attr = (const float*)d_in[6];
    const float* ntr_wq    = (const float*)d_in[7];
    const float* ntr_wkv   = (const float*)d_in[8];
    const float* ntr_wout  = (const float*)d_in[9];
    const float* ntr_g     = (const float*)d_in[10];
    const float* rtr_wqkv  = (const float*)d_in[11];
    const float* rtr_wout  = (const float*)d_in[12];
    const float* rtr_g     = (const float*)d_in[13];
    const float* ffn_win   = (const float*)d_in[14];
    const float* ffn_v     = (const float*)d_in[15];
    const float* ffn_wout  = (const float*)d_in[16];
    const float* ffn_g     = (const float*)d_in[17];
    const float* rtf_wq    = (const float*)d_in[18];
    const float* rtf_wkv   = (const float*)d_in[19];
    const float* rtf_wout  = (const float*)d_in[20];
    float* out = (float*)d_out;

    float *q, *k, *v, *kvtmp, *scores, *s, *agg, *x1, *x2, *tmp, *h1, *h2;
    cudaGetSymbolAddress((void**)&q,      g_q);
    cudaGetSymbolAddress((void**)&k,      g_k);
    cudaGetSymbolAddress((void**)&v,      g_v);
    cudaGetSymbolAddress((void**)&kvtmp,  g_kvtmp);
    cudaGetSymbolAddress((void**)&scores, g_scores);
    cudaGetSymbolAddress((void**)&s,      g_s);
    cudaGetSymbolAddress((void**)&agg,    g_agg);
    cudaGetSymbolAddress((void**)&x1,     g_x1);
    cudaGetSymbolAddress((void**)&x2,     g_x2);
    cudaGetSymbolAddress((void**)&tmp,    g_tmp);
    cudaGetSymbolAddress((void**)&h1,     g_h1);
    cudaGetSymbolAddress((void**)&h2,     g_h2);

    const float iscale = 0.17677669529663687f;  // 1/sqrt(32)
    const int edgeBlocks = EE / 8;
    const int resetBlocks = (NN * DD) / 256;
    const int ndBlocks = (NN * DD) / 256;
    const int nhBlocks = (NN * HH) / 256;

    // ===== stage 1: nodes_to_root CrossMHA + residual rmsnorm -> x1 =====
    tgemm_kernel<<<gg128(NN, DD), 256>>>(root, ntr_wq, q, NN, DD, DD);
    tgemm_kernel<<<gg128(NN, 2 * DD), 256>>>(node, ntr_wkv, kvtmp, NN, 2 * DD, DD);
    deint_kv_kernel<<<ndBlocks, 256>>>(kvtmp, k, v);
    reset_kernel<<<resetBlocks, 256>>>(s, agg);
    cross_scores_kernel<<<edgeBlocks, 256>>>(q, k, ntr_idx, ntr_idx + EE, scores, s, iscale);
    rcp_kernel<<<nhBlocks, 256>>>(s);
    agg_kernel<<<edgeBlocks, 256>>>(scores, s, v, ntr_idx, ntr_idx + EE, agg);
    tgemm_kernel<<<gg128(NN, DD), 256>>>(agg, ntr_wout, tmp, NN, DD, DD);
    add_rmsnorm_kernel<<<NN, 256>>>(root, tmp, ntr_g, x1);

    // ===== stage 2: roots_to_root SelfMHA + residual rmsnorm -> x2 =====
    tgemm_kernel<<<gg128(NN, 3 * DD), 256>>>(x1, rtr_wqkv, kvtmp, NN, 3 * DD, DD);
    deint_qkv_kernel<<<ndBlocks, 256>>>(kvtmp, q, k, v);
    reset_kernel<<<resetBlocks, 256>>>(s, agg);
    self_scores_kernel<<<edgeBlocks, 256>>>(q, k, edge_attr, rtr_idx, rtr_idx + EE, scores, s);
    rcp_kernel<<<nhBlocks, 256>>>(s);
    agg_kernel<<<edgeBlocks, 256>>>(scores, s, v, rtr_idx, rtr_idx + EE, agg);
    tgemm_kernel<<<gg128(NN, DD), 256>>>(agg, rtr_wout, tmp, NN, DD, DD);
    add_rmsnorm_kernel<<<NN, 256>>>(x1, tmp, rtr_g, x2);

    // ===== stage 3: SwiGLU FFN (on root_features) + residual rmsnorm -> out =====
    tgemm_kernel<<<gg128(NN, IM), 256>>>(root, ffn_win, h1, NN, IM, DD);
    tgemm_kernel<<<gg128(NN, IM), 256>>>(root, ffn_v, h2, NN, IM, DD);
    swiglu_act_kernel<<<(NN * IM + 255) / 256, 256>>>(h1, h2, NN * IM);
    tgemm_kernel<<<gg128(NN, DD), 256>>>(h1, ffn_wout, tmp, NN, DD, IM);
    add_rmsnorm_kernel<<<NN, 256>>>(tmp, x2, ffn_g, out);

    // ===== stage 4: root_to_fringe CrossMHA -> out[N*D : 2*N*D] =====
    tgemm_kernel<<<gg128(NN, DD), 256>>>(fringe, rtf_wq, q, NN, DD, DD);
    tgemm_kernel<<<gg128(NN, 2 * DD), 256>>>(root, rtf_wkv, kvtmp, NN, 2 * DD, DD);
    deint_kv_kernel<<<ndBlocks, 256>>>(kvtmp, k, v);
    reset_kernel<<<resetBlocks, 256>>>(s, agg);
    cross_scores_kernel<<<edgeBlocks, 256>>>(q, k, rtf_idx, rtf_idx + EE, scores, s, iscale);
    rcp_kernel<<<nhBlocks, 256>>>(s);
    agg_kernel<<<edgeBlocks, 256>>>(scores, s, v, rtf_idx, rtf_idx + EE, agg);
    tgemm_kernel<<<gg128(NN, DD), 256>>>(agg, rtf_wout, out + (size_t)NN * DD, NN, DD, DD);
}

// round 10
// speedup vs baseline: 1.7183x; 1.0402x over previous
#include <cuda_runtime.h>
#include <math.h>
#include <stdint.h>

// Problem constants (fixed by the dataset)
#define NN 16384      // nodes per set
#define DD 256        // model dim
#define EE 131072     // edges per relation
#define HH 8          // heads
#define HDIM 32       // head dim
#define IM 682        // SwiGLU intermediate

// ---------------- scratch (static device globals; no allocations) ----------
__device__ float g_q[NN * DD];          // q (contiguous [n][h*32+d])
__device__ float g_k[NN * DD];          // k
__device__ float g_v[NN * DD];          // v
__device__ float g_kvtmp[NN * 3 * DD];  // raw interleaved kv / qkv GEMM output
__device__ float g_scores[EE * HH];
__device__ float g_s[NN * HH];
__device__ float g_agg[NN * DD];
__device__ float g_x1[NN * DD];
__device__ float g_x2[NN * DD];
__device__ float g_tmp[NN * DD];
__device__ float g_h1[NN * IM];
__device__ float g_h2[NN * IM];

__device__ __forceinline__ uint32_t f2tf32(float f) {
    uint32_t r;
    asm("cvt.rna.tf32.f32 %0, %1;" : "=r"(r) : "f"(f));
    return r;
}

// ---------------- TF32 tensor-core GEMM: reg prefetch + double buffering ----
// C[M,N] = A[M,K] @ B[K,N], row-major fp32 in/out, tf32 mma.sync compute.
// 128x128 block tile, BK=32, 256 threads (8 warps), warp tile 64x32.
// Pipeline per tile: LDG(t+1) -> MMA(t) -> STS(t+1 into other buffer) -> 1 sync.
// Double-buffered smem (67.6 KB) lives in DYNAMIC shared memory (static cap is 48 KB).
#define BM 128
#define BN 128
#define BK 32
#define PAD 132   // padded row length (floats), proven conflict pattern
#define SM_BUF (BK * PAD)                     // words per (As|Bs) buffer
#define SMEM_BYTES (4 * SM_BUF * 2 * 2)       // 2 arrays x 2 buffers = 67584 B

__global__ __launch_bounds__(256)
void tgemm_kernel(const float* __restrict__ A, const float* __restrict__ B,
                  float* __restrict__ C, int M, int N, int K) {
    extern __shared__ uint32_t smem[];
    // layout: As[buf] at smem + buf*SM_BUF; Bs[buf] at smem + 2*SM_BUF + buf*SM_BUF
    uint32_t* AsBuf[2] = { smem,              smem + SM_BUF };
    uint32_t* BsBuf[2] = { smem + 2 * SM_BUF, smem + 3 * SM_BUF };

    const int tid  = threadIdx.x;
    const int lane = tid & 31;
    const int wid  = tid >> 5;            // 0..7
    const int warpM = wid & 1;            // 2 warps along M
    const int warpN = wid >> 1;           // 4 warps along N
    const int g   = lane >> 2;            // groupID 0..7
    const int tig = lane & 3;             // thread-in-group 0..3

    const int rowBase = blockIdx.y * BM;
    const int colBase = blockIdx.x * BN;

    float acc[4][4][4];
    #pragma unroll
    for (int i = 0; i < 4; i++)
        #pragma unroll
        for (int j = 0; j < 4; j++)
            #pragma unroll
            for (int r = 0; r < 4; r++) acc[i][j][r] = 0.0f;

    float2 aReg[8], bReg[8];
    const int T = (K + BK - 1) / BK;

    // ---- prologue: load tile 0 into registers, store to buffer 0
    #pragma unroll
    for (int i = 0; i < 8; i++) {
        int l  = tid + i * 256;
        int r  = l >> 4;
        int c2 = l & 15;
        int gr = rowBase + r, gk = 2 * c2;
        aReg[i] = (gr < M && gk < K) ? *(const float2*)(A + (size_t)gr * K + gk)
                                     : make_float2(0.0f, 0.0f);
    }
    #pragma unroll
    for (int i = 0; i < 8; i++) {
        int l  = tid + i * 256;
        int kk = l >> 6;
        int c2 = l & 63;
        int gk = kk, gc = colBase + 2 * c2;
        bReg[i] = (gk < K && gc < N) ? *(const float2*)(B + (size_t)gk * N + gc)
                                     : make_float2(0.0f, 0.0f);
    }
    {
        uint32_t* As0 = AsBuf[0];
        uint32_t* Bs0 = BsBuf[0];
        #pragma unroll
        for (int i = 0; i < 8; i++) {
            int l  = tid + i * 256;
            int r  = l >> 4;
            int c2 = l & 15;
            As0[(2 * c2) * PAD + r]     = f2tf32(aReg[i].x);
            As0[(2 * c2 + 1) * PAD + r] = f2tf32(aReg[i].y);
        }
        #pragma unroll
        for (int i = 0; i < 8; i++) {
            int l  = tid + i * 256;
            int kk = l >> 6;
            int c2 = l & 63;
            Bs0[kk * PAD + 2 * c2]     = f2tf32(bReg[i].x);
            Bs0[kk * PAD + 2 * c2 + 1] = f2tf32(bReg[i].y);
        }
    }
    __syncthreads();

    for (int t = 0; t < T; t++) {
        const int cur = t & 1, nxt = cur ^ 1;
        const uint32_t* As = AsBuf[cur];
        const uint32_t* Bs = BsBuf[cur];

        // ---- prefetch next tile into registers (overlaps compute below)
        if (t + 1 < T) {
            int k0 = (t + 1) * BK;
            #pragma unroll
            for (int i = 0; i < 8; i++) {
                int l  = tid + i * 256;
                int r  = l >> 4;
                int c2 = l & 15;
                int gr = rowBase + r, gk = k0 + 2 * c2;
                aReg[i] = (gr < M && gk < K) ? *(const float2*)(A + (size_t)gr * K + gk)
                                             : make_float2(0.0f, 0.0f);
            }
            #pragma unroll
            for (int i = 0; i < 8; i++) {
                int l  = tid + i * 256;
                int kk = l >> 6;
                int c2 = l & 63;
                int gk = k0 + kk, gc = colBase + 2 * c2;
                bReg[i] = (gk < K && gc < N) ? *(const float2*)(B + (size_t)gk * N + gc)
                                             : make_float2(0.0f, 0.0f);
            }
        }

        // ---- compute on current buffer: 4 k-atoms of 8
        #pragma unroll
        for (int ka = 0; ka < 4; ka++) {
            const int kb = ka * 8;
            uint32_t a[4][4], b[4][2];
            #pragma unroll
            for (int ma = 0; ma < 4; ma++) {
                int m0 = warpM * 64 + ma * 16;
                a[ma][0] = As[(kb + tig) * PAD + m0 + g];
                a[ma][1] = As[(kb + tig) * PAD + m0 + g + 8];
                a[ma][2] = As[(kb + tig + 4) * PAD + m0 + g];
                a[ma][3] = As[(kb + tig + 4) * PAD + m0 + g + 8];
            }
            #pragma unroll
            for (int na = 0; na < 4; na++) {
                int n0 = warpN * 32 + na * 8;
                b[na][0] = Bs[(kb + tig) * PAD + n0 + g];
                b[na][1] = Bs[(kb + tig + 4) * PAD + n0 + g];
            }
            #pragma unroll
            for (int ma = 0; ma < 4; ma++)
                #pragma unroll
                for (int na = 0; na < 4; na++) {
                    asm volatile(
                        "mma.sync.aligned.m16n8k8.row.col.f32.tf32.tf32.f32 "
                        "{%0,%1,%2,%3}, {%4,%5,%6,%7}, {%8,%9}, {%0,%1,%2,%3};\n"
                        : "+f"(acc[ma][na][0]), "+f"(acc[ma][na][1]),
                          "+f"(acc[ma][na][2]), "+f"(acc[ma][na][3])
                        : "r"(a[ma][0]), "r"(a[ma][1]), "r"(a[ma][2]), "r"(a[ma][3]),
                          "r"(b[na][0]), "r"(b[na][1]));
                }
        }

        // ---- store prefetched tile into the other buffer
        if (t + 1 < T) {
            uint32_t* An = AsBuf[nxt];
            uint32_t* Bn = BsBuf[nxt];
            #pragma unroll
            for (int i = 0; i < 8; i++) {
                int l  = tid + i * 256;
                int r  = l >> 4;
                int c2 = l & 15;
                An[(2 * c2) * PAD + r]     = f2tf32(aReg[i].x);
                An[(2 * c2 + 1) * PAD + r] = f2tf32(aReg[i].y);
            }
            #pragma unroll
            for (int i = 0; i < 8; i++) {
                int l  = tid + i * 256;
                int kk = l >> 6;
                int c2 = l & 63;
                Bn[kk * PAD + 2 * c2]     = f2tf32(bReg[i].x);
                Bn[kk * PAD + 2 * c2 + 1] = f2tf32(bReg[i].y);
            }
        }
        __syncthreads();   // next buffer ready; everyone done with cur
    }

    // ---- store C (float2 per row-half of each atom); N even -> alignment OK
    #pragma unroll
    for (int ma = 0; ma < 4; ma++) {
        int r0 = rowBase + warpM * 64 + ma * 16 + g;
        #pragma unroll
        for (int na = 0; na < 4; na++) {
            int c = colBase + warpN * 32 + na * 8 + tig * 2;
            if (c < N) {
                if (r0 < M)
                    *(float2*)(C + (size_t)r0 * N + c) = make_float2(acc[ma][na][0], acc[ma][na][1]);
                if (r0 + 8 < M)
                    *(float2*)(C + (size_t)(r0 + 8) * N + c) = make_float2(acc[ma][na][2], acc[ma][na][3]);
            }
        }
    }
}

// ---------------- de-interleave kernels -------------------------------------
// kv [n][h*64 + 2d + {0:k,1:v}] -> k[n][h*32+d], v[n][h*32+d]
__global__ void deint_kv_kernel(const float* __restrict__ kv,
                                float* __restrict__ k, float* __restrict__ v) {
    int i = blockIdx.x * blockDim.x + threadIdx.x;   // NN*DD threads
    int n = i >> 8, j = i & 255;
    int h = j >> 5, d = j & 31;
    float2 p = *(const float2*)(kv + (size_t)n * 512 + h * 64 + 2 * d);
    k[i] = p.x;
    v[i] = p.y;
}

// qkv [n][h*96 + 3d + {0:q,1:k,2:v}] -> q,k,v [n][h*32+d]
__global__ void deint_qkv_kernel(const float* __restrict__ qkv,
                                 float* __restrict__ q, float* __restrict__ k,
                                 float* __restrict__ v) {
    int i = blockIdx.x * blockDim.x + threadIdx.x;   // NN*DD threads
    int n = i >> 8, j = i & 255;
    int h = j >> 5, d = j & 31;
    const float* p = qkv + (size_t)n * 768 + h * 96 + 3 * d;
    q[i] = p[0];
    k[i] = p[1];
    v[i] = p[2];
}

// ---------------- reciprocal of softmax denominators ------------------------
__global__ void rcp_kernel(float* __restrict__ s) {
    int i = blockIdx.x * blockDim.x + threadIdx.x;
    if (i < NN * HH) s[i] = __frcp_rn(s[i]);
}

// ---------------- edge kernels (contiguous [n][h*32+d] layouts) -------------
// Scores: warp per edge; 4 lanes per head; lane handles 8 consecutive dims.
// No max-subtraction: scores are O(10), exp safe in fp32; softmax is
// shift-invariant so the result matches the reference.
__global__ void cross_scores_kernel(const float* __restrict__ Q, const float* __restrict__ Kk,
                                    const int* __restrict__ src, const int* __restrict__ dst,
                                    float* __restrict__ scores, float* __restrict__ s,
                                    float scale) {
    int e = (blockIdx.x * blockDim.x + threadIdx.x) >> 5;
    int lane = threadIdx.x & 31;
    if (e >= EE) return;
    int sn = src[e], tn = dst[e];
    const float4* q4 = (const float4*)(Q  + (size_t)tn * DD);
    const float4* k4 = (const float4*)(Kk + (size_t)sn * DD);
    float4 qa = q4[2 * lane], qb = q4[2 * lane + 1];
    float4 ka = k4[2 * lane], kb = k4[2 * lane + 1];
    float p = qa.x * ka.x + qa.y * ka.y + qa.z * ka.z + qa.w * ka.w
            + qb.x * kb.x + qb.y * kb.y + qb.z * kb.z + qb.w * kb.w;
    p += __shfl_xor_sync(0xFFFFFFFFu, p, 1);
    p += __shfl_xor_sync(0xFFFFFFFFu, p, 2);
    if ((lane & 3) == 0) {
        int h = lane >> 2;
        float ev = __expf(p * scale);
        scores[(size_t)e * HH + h] = ev;
        atomicAdd(&s[tn * HH + h], ev);
    }
}

__global__ void self_scores_kernel(const float* __restrict__ Q, const float* __restrict__ Kk,
                                   const float* __restrict__ attr,
                                   const int* __restrict__ src, const int* __restrict__ dst,
                                   float* __restrict__ scores, float* __restrict__ s) {
    int e = (blockIdx.x * blockDim.x + threadIdx.x) >> 5;
    int lane = threadIdx.x & 31;
    if (e >= EE) return;
    int sn = src[e], tn = dst[e];
    const float4* q4 = (const float4*)(Q    + (size_t)tn * DD);
    const float4* k4 = (const float4*)(Kk   + (size_t)sn * DD);
    const float4* a4 = (const float4*)(attr + (size_t)e  * DD);
    float4 qa = q4[2 * lane], qb = q4[2 * lane + 1];
    float4 ka = k4[2 * lane], kb = k4[2 * lane + 1];
    float4 aa = a4[2 * lane], ab = a4[2 * lane + 1];
    float p = qa.x * ka.x * aa.x + qa.y * ka.y * aa.y + qa.z * ka.z * aa.z + qa.w * ka.w * aa.w
            + qb.x * kb.x * ab.x + qb.y * kb.y * ab.y + qb.z * kb.z * ab.z + qb.w * kb.w * ab.w;
    p += __shfl_xor_sync(0xFFFFFFFFu, p, 1);
    p += __shfl_xor_sync(0xFFFFFFFFu, p, 2);
    if ((lane & 3) == 0) {
        int h = lane >> 2;
        float ev = __expf(p);   // no 1/sqrt(hd) in SelfMHA
        scores[(size_t)e * HH + h] = ev;
        atomicAdd(&s[tn * HH + h], ev);
    }
}

// Agg: warp per edge, loop over heads; each atomic instruction's 32 lanes are
// CONTIGUOUS (h*32+lane) -> 1-2 cache lines per instruction.
__global__ void agg_kernel(const float* __restrict__ scores, const float* __restrict__ rsum,
                           const float* __restrict__ V,
                           const int* __restrict__ src, const int* __restrict__ dst,
                           float* __restrict__ agg) {
    int e = (blockIdx.x * blockDim.x + threadIdx.x) >> 5;
    int lane = threadIdx.x & 31;
    if (e >= EE) return;
    int sn = src[e], tn = dst[e];
    const float* vp = V   + (size_t)sn * DD;
    float*       ap = agg + (size_t)tn * DD;
    const float* sp = scores + (size_t)e * HH;
    const float* rp = rsum + tn * HH;
    #pragma unroll
    for (int h = 0; h < HH; h++) {
        float w = sp[h] * rp[h];
        atomicAdd(ap + h * HDIM + lane, w * vp[h * HDIM + lane]);
    }
}

// ---------------- residual + RMSNorm: out = rmsnorm(a+b) * g ----------------
__global__ void add_rmsnorm_kernel(const float* __restrict__ a, const float* __restrict__ b,
                                   const float* __restrict__ g, float* __restrict__ out) {
    int row = blockIdx.x;
    int d = threadIdx.x;
    float x = a[(size_t)row * DD + d] + b[(size_t)row * DD + d];
    float v = x * x;
    __shared__ float red[8];
    #pragma unroll
    for (int o = 16; o; o >>= 1) v += __shfl_xor_sync(0xFFFFFFFFu, v, o);
    if ((d & 31) == 0) red[d >> 5] = v;
    __syncthreads();
    if (d < 8) {
        float t = red[d];
        #pragma unroll
        for (int o = 4; o; o >>= 1) t += __shfl_xor_sync(0xFFu, t, o);
        if (d == 0) red[0] = t;
    }
    __syncthreads();
    float norm = sqrtf(red[0]) * 0.0625f;
    float inv = 1.0f / fmaxf(norm, 1e-8f);
    out[(size_t)row * DD + d] = x * inv * g[d];
}

// ---------------- SwiGLU activation -----------------------------------------
__global__ void swiglu_act_kernel(float* __restrict__ h1, const float* __restrict__ h2, int n) {
    int i = blockIdx.x * blockDim.x + threadIdx.x;
    if (i >= n) return;
    float x = h1[i];
    h1[i] = x * (1.0f / (1.0f + __expf(-x))) * h2[i];
}

// ---------------- launch ----------------------------------------------------
static inline dim3 gg128(int M, int Ncols) { return dim3((Ncols + 127) / 128, (M + 127) / 128); }

extern "C" void kernel_launch(void* const* d_in, const int* in_sizes, int n_in,
                              void* d_out, int out_size) {
    const float* root      = (const float*)d_in[0];
    const float* node      = (const float*)d_in[1];
    const float* fringe    = (const float*)d_in[2];
    const int*   ntr_idx   = (const int*)d_in[3];
    const int*   rtr_idx   = (const int*)d_in[4];
    const int*   rtf_idx   = (const int*)d_in[5];
    const float* edge_attr = (const float*)d_in[6];
    const float* ntr_wq    = (const float*)d_in[7];
    const float* ntr_wkv   = (const float*)d_in[8];
    const float* ntr_wout  = (const float*)d_in[9];
    const float* ntr_g     = (const float*)d_in[10];
    const float* rtr_wqkv  = (const float*)d_in[11];
    const float* rtr_wout  = (const float*)d_in[12];
    const float* rtr_g     = (const float*)d_in[13];
    const float* ffn_win   = (const float*)d_in[14];
    const float* ffn_v     = (const float*)d_in[15];
    const float* ffn_wout  = (const float*)d_in[16];
    const float* ffn_g     = (const float*)d_in[17];
    const float* rtf_wq    = (const float*)d_in[18];
    const float* rtf_wkv   = (const float*)d_in[19];
    const float* rtf_wout  = (const float*)d_in[20];
    float* out = (float*)d_out;

    float *q, *k, *v, *kvtmp, *scores, *s, *agg, *x1, *x2, *tmp, *h1, *h2;
    cudaGetSymbolAddress((void**)&q,      g_q);
    cudaGetSymbolAddress((void**)&k,      g_k);
    cudaGetSymbolAddress((void**)&v,      g_v);
    cudaGetSymbolAddress((void**)&kvtmp,  g_kvtmp);
    cudaGetSymbolAddress((void**)&scores, g_scores);
    cudaGetSymbolAddress((void**)&s,      g_s);
    cudaGetSymbolAddress((void**)&agg,    g_agg);
    cudaGetSymbolAddress((void**)&x1,     g_x1);
    cudaGetSymbolAddress((void**)&x2,     g_x2);
    cudaGetSymbolAddress((void**)&tmp,    g_tmp);
    cudaGetSymbolAddress((void**)&h1,     g_h1);
    cudaGetSymbolAddress((void**)&h2,     g_h2);

    // allow 67.6 KB dynamic smem for the double-buffered GEMM (idempotent)
    cudaFuncSetAttribute(tgemm_kernel, cudaFuncAttributeMaxDynamicSharedMemorySize, SMEM_BYTES);

    const float iscale = 0.17677669529663687f;  // 1/sqrt(32)
    const int edgeBlocks = EE / 8;
    const int ndBlocks = (NN * DD) / 256;
    const int nhBlocks = (NN * HH) / 256;

    // ===== stage 1: nodes_to_root CrossMHA + residual rmsnorm -> x1 =====
    tgemm_kernel<<<gg128(NN, DD), 256, SMEM_BYTES>>>(root, ntr_wq, q, NN, DD, DD);
    tgemm_kernel<<<gg128(NN, 2 * DD), 256, SMEM_BYTES>>>(node, ntr_wkv, kvtmp, NN, 2 * DD, DD);
    deint_kv_kernel<<<ndBlocks, 256>>>(kvtmp, k, v);
    cudaMemsetAsync(agg, 0, (size_t)NN * DD * sizeof(float));
    cudaMemsetAsync(s, 0, (size_t)NN * HH * sizeof(float));
    cross_scores_kernel<<<edgeBlocks, 256>>>(q, k, ntr_idx, ntr_idx + EE, scores, s, iscale);
    rcp_kernel<<<nhBlocks, 256>>>(s);
    agg_kernel<<<edgeBlocks, 256>>>(scores, s, v, ntr_idx, ntr_idx + EE, agg);
    tgemm_kernel<<<gg128(NN, DD), 256, SMEM_BYTES>>>(agg, ntr_wout, tmp, NN, DD, DD);
    add_rmsnorm_kernel<<<NN, 256>>>(root, tmp, ntr_g, x1);

    // ===== stage 2: roots_to_root SelfMHA + residual rmsnorm -> x2 =====
    tgemm_kernel<<<gg128(NN, 3 * DD), 256, SMEM_BYTES>>>(x1, rtr_wqkv, kvtmp, NN, 3 * DD, DD);
    deint_qkv_kernel<<<ndBlocks, 256>>>(kvtmp, q, k, v);
    cudaMemsetAsync(agg, 0, (size_t)NN * DD * sizeof(float));
    cudaMemsetAsync(s, 0, (size_t)NN * HH * sizeof(float));
    self_scores_kernel<<<edgeBlocks, 256>>>(q, k, edge_attr, rtr_idx, rtr_idx + EE, scores, s);
    rcp_kernel<<<nhBlocks, 256>>>(s);
    agg_kernel<<<edgeBlocks, 256>>>(scores, s, v, rtr_idx, rtr_idx + EE, agg);
    tgemm_kernel<<<gg128(NN, DD), 256, SMEM_BYTES>>>(agg, rtr_wout, tmp, NN, DD, DD);
    add_rmsnorm_kernel<<<NN, 256>>>(x1, tmp, rtr_g, x2);

    // ===== stage 3: SwiGLU FFN (on root_features) + residual rmsnorm -> out =====
    tgemm_kernel<<<gg128(NN, IM), 256, SMEM_BYTES>>>(root, ffn_win, h1, NN, IM, DD);
    tgemm_kernel<<<gg128(NN, IM), 256, SMEM_BYTES>>>(root, ffn_v, h2, NN, IM, DD);
    swiglu_act_kernel<<<(NN * IM + 255) / 256, 256>>>(h1, h2, NN * IM);
    tgemm_kernel<<<gg128(NN, DD), 256, SMEM_BYTES>>>(h1, ffn_wout, tmp, NN, DD, IM);
    add_rmsnorm_kernel<<<NN, 256>>>(tmp, x2, ffn_g, out);

    // ===== stage 4: root_to_fringe CrossMHA -> out[N*D : 2*N*D] =====
    tgemm_kernel<<<gg128(NN, DD), 256, SMEM_BYTES>>>(fringe, rtf_wq, q, NN, DD, DD);
    tgemm_kernel<<<gg128(NN, 2 * DD), 256, SMEM_BYTES>>>(root, rtf_wkv, kvtmp, NN, 2 * DD, DD);
    deint_kv_kernel<<<ndBlocks, 256>>>(kvtmp, k, v);
    cudaMemsetAsync(agg, 0, (size_t)NN * DD * sizeof(float));
    cudaMemsetAsync(s, 0, (size_t)NN * HH * sizeof(float));
    cross_scores_kernel<<<edgeBlocks, 256>>>(q, k, rtf_idx, rtf_idx + EE, scores, s, iscale);
    rcp_kernel<<<nhBlocks, 256>>>(s);
    agg_kernel<<<edgeBlocks, 256>>>(scores, s, v, rtf_idx, rtf_idx + EE, agg);
    tgemm_kernel<<<gg128(NN, DD), 256, SMEM_BYTES>>>(agg, rtf_wout, out + (size_t)NN * DD, NN, DD, DD);
}